// round 2
// baseline (speedup 1.0000x reference)
#include <cuda_runtime.h>
#include <cuda_bf16.h>
#include <math.h>

// ---------------------------------------------------------------------------
// GCN 3-layer: support = h@W ; agg = segment_sum(support[edge_dst]*edge_vals,
// edge_src) ; out = agg + b (relu for layers 1,2). Heads: log_softmax(L3),
// h2@We+be.
//
// Strategy (round 0):
//   * Build CSR keyed by edge_src on-device every call (hist + 1-block scan +
//     scatter). Feature aggregation is then gather-side, atomic-free.
//   * Classic tiled fp32 SGEMM (templated) for the 4 dense GEMMs.
//   * Warp-per-node SpMM (float4 lanes for D=128, float2 for D=64, 16-lane
//     groups for D=16) with fused bias(+ReLU) epilogue.
// ---------------------------------------------------------------------------

#define NN 50000
#define EE 800000

// scratch (device globals: no allocation allowed)
__device__ float g_support[NN * 128];  // support of current layer (max D=128)
__device__ float g_h1[NN * 128];
__device__ float g_h2[NN * 64];
__device__ float g_g3[NN * 16];
__device__ int   g_counts[NN + 1];
__device__ int   g_offsets[NN + 1];
__device__ int   g_cursor[NN];
__device__ int   g_col[EE];
__device__ float g_val[EE];

// ------------------------------ CSR build ----------------------------------

__global__ void hist_kernel(const int* __restrict__ src, int* __restrict__ counts, int E) {
    int i = blockIdx.x * blockDim.x + threadIdx.x;
    if (i < E) atomicAdd(&counts[src[i]], 1);
}

// single-block exclusive scan over n elements (n up to ~64k fine)
__global__ void scan_kernel(const int* __restrict__ counts, int* __restrict__ offsets, int n) {
    __shared__ int s[1024];
    __shared__ int carry_s;
    int tid = threadIdx.x;
    if (tid == 0) carry_s = 0;
    __syncthreads();
    for (int base = 0; base < n; base += 1024) {
        int i = base + tid;
        int v = (i < n) ? counts[i] : 0;
        s[tid] = v;
        __syncthreads();
        #pragma unroll
        for (int off = 1; off < 1024; off <<= 1) {
            int t = (tid >= off) ? s[tid - off] : 0;
            __syncthreads();
            s[tid] += t;
            __syncthreads();
        }
        int carry = carry_s;
        if (i < n) offsets[i] = carry + s[tid] - v;  // exclusive
        __syncthreads();
        if (tid == 1023) carry_s = carry + s[1023];
        __syncthreads();
    }
    if (tid == 0) offsets[n] = carry_s;
}

__global__ void scatter_kernel(const int* __restrict__ src, const int* __restrict__ dst,
                               const float* __restrict__ ev,
                               const int* __restrict__ offsets, int* __restrict__ cursor,
                               int* __restrict__ col, float* __restrict__ val, int E) {
    int i = blockIdx.x * blockDim.x + threadIdx.x;
    if (i < E) {
        int s = src[i];
        int pos = offsets[s] + atomicAdd(&cursor[s], 1);
        col[pos] = dst[i];
        val[pos] = ev[i];
    }
}

// ------------------------------ tiled SGEMM --------------------------------
// C[M,N] = A[M,K] @ B[K,N] (+ bias[N] if BIAS). Row-major everywhere.

template <int BM, int BN, int BK, int TM, int TN, bool BIAS>
__global__ void sgemm_kernel(int M, int N, int K,
                             const float* __restrict__ A,
                             const float* __restrict__ B,
                             const float* __restrict__ bias,
                             float* __restrict__ C) {
    constexpr int THREADS = (BM / TM) * (BN / TN);
    __shared__ float As[BK][BM];
    __shared__ float Bs[BK][BN];

    const int row0 = blockIdx.y * BM;
    const int col0 = blockIdx.x * BN;
    const int tid = threadIdx.x;
    const int tr = tid / (BN / TN);
    const int tc = tid % (BN / TN);

    float acc[TM][TN];
    #pragma unroll
    for (int i = 0; i < TM; i++)
        #pragma unroll
        for (int j = 0; j < TN; j++) acc[i][j] = 0.f;

    for (int k0 = 0; k0 < K; k0 += BK) {
        for (int idx = tid; idx < BM * BK; idx += THREADS) {
            int m = idx / BK, kk = idx % BK;
            int gm = row0 + m, gk = k0 + kk;
            As[kk][m] = (gm < M && gk < K) ? A[(long)gm * K + gk] : 0.f;
        }
        for (int idx = tid; idx < BK * BN; idx += THREADS) {
            int kk = idx / BN, nn = idx % BN;
            int gk = k0 + kk, gn = col0 + nn;
            Bs[kk][nn] = (gk < K && gn < N) ? B[(long)gk * N + gn] : 0.f;
        }
        __syncthreads();
        #pragma unroll
        for (int kk = 0; kk < BK; kk++) {
            float ar[TM], br[TN];
            #pragma unroll
            for (int i = 0; i < TM; i++) ar[i] = As[kk][tr * TM + i];
            #pragma unroll
            for (int j = 0; j < TN; j++) br[j] = Bs[kk][tc * TN + j];
            #pragma unroll
            for (int i = 0; i < TM; i++)
                #pragma unroll
                for (int j = 0; j < TN; j++) acc[i][j] += ar[i] * br[j];
        }
        __syncthreads();
    }

    #pragma unroll
    for (int i = 0; i < TM; i++) {
        int gm = row0 + tr * TM + i;
        if (gm >= M) continue;
        #pragma unroll
        for (int j = 0; j < TN; j++) {
            int gn = col0 + tc * TN + j;
            if (gn < N) {
                float v = acc[i][j];
                if (BIAS) v += bias[gn];
                C[(long)gm * N + gn] = v;
            }
        }
    }
}

// ------------------------------ CSR SpMM -----------------------------------
// out[i,:] = (sum_{j in seg(i)} val[j] * support[col[j],:]) + bias ; opt ReLU.

template <bool RELU>
__global__ void spmm128_kernel(const float* __restrict__ support,
                               const int* __restrict__ offsets,
                               const int* __restrict__ col,
                               const float* __restrict__ val,
                               const float* __restrict__ bias,
                               float* __restrict__ out, int n) {
    int warp = (blockIdx.x * blockDim.x + threadIdx.x) >> 5;
    int lane = threadIdx.x & 31;
    if (warp >= n) return;
    int start = offsets[warp], end = offsets[warp + 1];
    const float4* sup4 = (const float4*)support;
    float4 acc = make_float4(0.f, 0.f, 0.f, 0.f);
    for (int j = start; j < end; j++) {
        int c = col[j];
        float w = val[j];
        float4 s = sup4[c * 32 + lane];
        acc.x += w * s.x; acc.y += w * s.y; acc.z += w * s.z; acc.w += w * s.w;
    }
    float4 bb = ((const float4*)bias)[lane];
    acc.x += bb.x; acc.y += bb.y; acc.z += bb.z; acc.w += bb.w;
    if (RELU) {
        acc.x = fmaxf(acc.x, 0.f); acc.y = fmaxf(acc.y, 0.f);
        acc.z = fmaxf(acc.z, 0.f); acc.w = fmaxf(acc.w, 0.f);
    }
    ((float4*)out)[warp * 32 + lane] = acc;
}

template <bool RELU>
__global__ void spmm64_kernel(const float* __restrict__ support,
                              const int* __restrict__ offsets,
                              const int* __restrict__ col,
                              const float* __restrict__ val,
                              const float* __restrict__ bias,
                              float* __restrict__ out, int n) {
    int warp = (blockIdx.x * blockDim.x + threadIdx.x) >> 5;
    int lane = threadIdx.x & 31;
    if (warp >= n) return;
    int start = offsets[warp], end = offsets[warp + 1];
    const float2* sup2 = (const float2*)support;
    float2 acc = make_float2(0.f, 0.f);
    for (int j = start; j < end; j++) {
        int c = col[j];
        float w = val[j];
        float2 s = sup2[c * 32 + lane];
        acc.x += w * s.x; acc.y += w * s.y;
    }
    float2 bb = ((const float2*)bias)[lane];
    acc.x += bb.x; acc.y += bb.y;
    if (RELU) { acc.x = fmaxf(acc.x, 0.f); acc.y = fmaxf(acc.y, 0.f); }
    ((float2*)out)[warp * 32 + lane] = acc;
}

__global__ void spmm16_kernel(const float* __restrict__ support,
                              const int* __restrict__ offsets,
                              const int* __restrict__ col,
                              const float* __restrict__ val,
                              const float* __restrict__ bias,
                              float* __restrict__ out, int n) {
    int t = blockIdx.x * blockDim.x + threadIdx.x;
    int grp = t >> 4;
    int sub = t & 15;
    if (grp >= n) return;
    int start = offsets[grp], end = offsets[grp + 1];
    float acc = 0.f;
    for (int j = start; j < end; j++) {
        acc += val[j] * support[col[j] * 16 + sub];
    }
    out[grp * 16 + sub] = acc + bias[sub];
}

// ------------------------------ log-softmax --------------------------------

__global__ void logsoftmax16_kernel(const float* __restrict__ in, float* __restrict__ out, int n) {
    int i = blockIdx.x * blockDim.x + threadIdx.x;
    if (i >= n) return;
    float v[16];
    const float4* in4 = (const float4*)(in + i * 16);
    #pragma unroll
    for (int q = 0; q < 4; q++) {
        float4 f = in4[q];
        v[q * 4 + 0] = f.x; v[q * 4 + 1] = f.y; v[q * 4 + 2] = f.z; v[q * 4 + 3] = f.w;
    }
    float m = v[0];
    #pragma unroll
    for (int f = 1; f < 16; f++) m = fmaxf(m, v[f]);
    float s = 0.f;
    #pragma unroll
    for (int f = 0; f < 16; f++) s += expf(v[f] - m);
    float l = logf(s) + m;
    float4* out4 = (float4*)(out + i * 16);
    #pragma unroll
    for (int q = 0; q < 4; q++) {
        float4 f;
        f.x = v[q * 4 + 0] - l; f.y = v[q * 4 + 1] - l;
        f.z = v[q * 4 + 2] - l; f.w = v[q * 4 + 3] - l;
        out4[q] = f;
    }
}

// ------------------------------ launch -------------------------------------

extern "C" void kernel_launch(void* const* d_in, const int* in_sizes, int n_in,
                              void* d_out, int out_size) {
    const float* x  = (const float*)d_in[0];
    const float* ev = (const float*)d_in[1];
    const float* W1 = (const float*)d_in[2];
    const float* b1 = (const float*)d_in[3];
    const float* W2 = (const float*)d_in[4];
    const float* b2 = (const float*)d_in[5];
    const float* W3 = (const float*)d_in[6];
    const float* b3 = (const float*)d_in[7];
    const float* We = (const float*)d_in[8];
    const float* be = (const float*)d_in[9];
    const int* esrc = (const int*)d_in[10];
    const int* edst = (const int*)d_in[11];

    const int N = NN;
    const int E = in_sizes[10];

    float* out1 = (float*)d_out;               // [N,16]
    float* out2 = (float*)d_out + (long)N * 16;  // [N,64]

    float *p_support, *p_h1, *p_h2, *p_g3, *p_val;
    int *p_counts, *p_offsets, *p_cursor, *p_col;
    cudaGetSymbolAddress((void**)&p_support, g_support);
    cudaGetSymbolAddress((void**)&p_h1, g_h1);
    cudaGetSymbolAddress((void**)&p_h2, g_h2);
    cudaGetSymbolAddress((void**)&p_g3, g_g3);
    cudaGetSymbolAddress((void**)&p_counts, g_counts);
    cudaGetSymbolAddress((void**)&p_offsets, g_offsets);
    cudaGetSymbolAddress((void**)&p_cursor, g_cursor);
    cudaGetSymbolAddress((void**)&p_col, g_col);
    cudaGetSymbolAddress((void**)&p_val, g_val);

    // ---- CSR build ----
    cudaMemsetAsync(p_counts, 0, (N + 1) * sizeof(int), 0);
    cudaMemsetAsync(p_cursor, 0, N * sizeof(int), 0);
    hist_kernel<<<(E + 255) / 256, 256>>>(esrc, p_counts, E);
    scan_kernel<<<1, 1024>>>(p_counts, p_offsets, N);
    scatter_kernel<<<(E + 255) / 256, 256>>>(esrc, edst, ev, p_offsets, p_cursor, p_col, p_val, E);

    // ---- layer 1: support = x@W1 [N,128]; h1 = relu(agg + b1) ----
    {
        dim3 grid(1, (N + 127) / 128);
        sgemm_kernel<128, 128, 8, 8, 8, false><<<grid, 256>>>(N, 128, 500, x, W1, nullptr, p_support);
        spmm128_kernel<true><<<(N * 32 + 255) / 256, 256>>>(p_support, p_offsets, p_col, p_val, b1, p_h1, N);
    }
    // ---- layer 2: support = h1@W2 [N,64]; h2 = relu(agg + b2) ----
    {
        dim3 grid(1, (N + 127) / 128);
        sgemm_kernel<128, 64, 8, 8, 8, false><<<grid, 128>>>(N, 64, 128, p_h1, W2, nullptr, p_support);
        spmm64_kernel<true><<<(N * 32 + 255) / 256, 256>>>(p_support, p_offsets, p_col, p_val, b2, p_h2, N);
    }
    // ---- layer 3: support = h2@W3 [N,16]; g3 = agg + b3; out1 = logsoftmax ----
    {
        dim3 grid(1, (N + 63) / 64);
        sgemm_kernel<64, 16, 8, 4, 2, false><<<grid, 128>>>(N, 16, 64, p_h2, W3, nullptr, p_support);
        spmm16_kernel<<<(N * 16 + 255) / 256, 256>>>(p_support, p_offsets, p_col, p_val, b3, p_g3, N);
        logsoftmax16_kernel<<<(N + 255) / 256, 256>>>(p_g3, out1, N);
    }
    // ---- head 2: out2 = h2@We + be ----
    {
        dim3 grid(1, (N + 127) / 128);
        sgemm_kernel<128, 64, 8, 8, 8, true><<<grid, 128>>>(N, 64, 64, p_h2, We, be, out2);
    }
}

// round 3
// speedup vs baseline: 2.5684x; 2.5684x over previous
#include <cuda_runtime.h>
#include <cuda_bf16.h>
#include <math.h>

// ---------------------------------------------------------------------------
// GCN 3-layer. Round 1: all dense GEMMs on tensor cores (mma.sync m16n8k8
// tf32) with 2-term tf32 split for fp32-level accuracy. CSR build + gather-
// side SpMM unchanged from round 0.
// ---------------------------------------------------------------------------

#define NN 50000
#define EE 800000

__device__ float g_support[NN * 128];
__device__ float g_h1[NN * 128];
__device__ float g_h2[NN * 64];
__device__ float g_g3[NN * 16];
__device__ int   g_counts[NN + 1];
__device__ int   g_offsets[NN + 1];
__device__ int   g_cursor[NN];
__device__ int   g_col[EE];
__device__ float g_val[EE];

// ------------------------------ CSR build ----------------------------------

__global__ void hist_kernel(const int* __restrict__ src, int* __restrict__ counts, int E) {
    int i = blockIdx.x * blockDim.x + threadIdx.x;
    if (i < E) atomicAdd(&counts[src[i]], 1);
}

__global__ void scan_kernel(const int* __restrict__ counts, int* __restrict__ offsets, int n) {
    __shared__ int s[1024];
    __shared__ int carry_s;
    int tid = threadIdx.x;
    if (tid == 0) carry_s = 0;
    __syncthreads();
    for (int base = 0; base < n; base += 1024) {
        int i = base + tid;
        int v = (i < n) ? counts[i] : 0;
        s[tid] = v;
        __syncthreads();
        #pragma unroll
        for (int off = 1; off < 1024; off <<= 1) {
            int t = (tid >= off) ? s[tid - off] : 0;
            __syncthreads();
            s[tid] += t;
            __syncthreads();
        }
        int carry = carry_s;
        if (i < n) offsets[i] = carry + s[tid] - v;
        __syncthreads();
        if (tid == 1023) carry_s = carry + s[1023];
        __syncthreads();
    }
    if (tid == 0) offsets[n] = carry_s;
}

__global__ void scatter_kernel(const int* __restrict__ src, const int* __restrict__ dst,
                               const float* __restrict__ ev,
                               const int* __restrict__ offsets, int* __restrict__ cursor,
                               int* __restrict__ col, float* __restrict__ val, int E) {
    int i = blockIdx.x * blockDim.x + threadIdx.x;
    if (i < E) {
        int s = src[i];
        int pos = offsets[s] + atomicAdd(&cursor[s], 1);
        col[pos] = dst[i];
        val[pos] = ev[i];
    }
}

// ------------------------------ tf32 GEMM ----------------------------------
// C[M,N] = A[M,K] @ B[K,N] (+bias). mma.sync m16n8k8 tf32 with hi/lo split.
// Requires N == BN (grid.x == 1), K % 4 == 0.

__device__ __forceinline__ void split_tf32(float x, unsigned& hi, unsigned& lo) {
    unsigned h;
    asm("cvt.rna.tf32.f32 %0, %1;" : "=r"(h) : "f"(x));
    float r = x - __uint_as_float(h);
    unsigned l;
    asm("cvt.rna.tf32.f32 %0, %1;" : "=r"(l) : "f"(r));
    hi = h; lo = l;
}

#define MMA_TF32(c, a, b)                                                    \
    asm volatile(                                                            \
        "mma.sync.aligned.m16n8k8.row.col.f32.tf32.tf32.f32 "                \
        "{%0,%1,%2,%3}, {%4,%5,%6,%7}, {%8,%9}, {%0,%1,%2,%3};\n"            \
        : "+f"((c)[0]), "+f"((c)[1]), "+f"((c)[2]), "+f"((c)[3])             \
        : "r"((a)[0]), "r"((a)[1]), "r"((a)[2]), "r"((a)[3]),                \
          "r"((b)[0]), "r"((b)[1]))

template <int BM, int BN, int BK, int WARPS_M, int WARPS_N, bool BIAS>
__global__ void __launch_bounds__(32 * WARPS_M * WARPS_N)
tf32_gemm_kernel(int M, int N, int K,
                 const float* __restrict__ A, const float* __restrict__ B,
                 const float* __restrict__ bias, float* __restrict__ C) {
    constexpr int THREADS = 32 * WARPS_M * WARPS_N;
    constexpr int WM = BM / WARPS_M, WN = BN / WARPS_N;
    constexpr int MT = WM / 16, NT = WN / 8;
    constexpr int SA = BK + 4;   // A smem row stride (conflict-free for frag reads)
    constexpr int SB = BN + 8;   // B smem row stride
    constexpr int A4 = BM * BK / 4, B4 = BK * BN / 4;
    constexpr int RA = (A4 + THREADS - 1) / THREADS;
    constexpr int RB = (B4 + THREADS - 1) / THREADS;

    __shared__ float Ah[BM * SA], Al[BM * SA];
    __shared__ float Bh[BK * SB], Bl[BK * SB];

    const int tid = threadIdx.x;
    const int warp = tid >> 5, lane = tid & 31;
    const int wm = (warp / WARPS_N) * WM;
    const int wn = (warp % WARPS_N) * WN;
    const int g = lane >> 2, t = lane & 3;
    const int row0 = blockIdx.y * BM;

    float acc[MT][NT][4];
    #pragma unroll
    for (int mi = 0; mi < MT; mi++)
        #pragma unroll
        for (int ni = 0; ni < NT; ni++)
            #pragma unroll
            for (int q = 0; q < 4; q++) acc[mi][ni][q] = 0.f;

    float4 ra[RA], rb[RB];

    const int ntiles = (K + BK - 1) / BK;

    // --- load tile k0 into regs ---
    auto load_tile = [&](int k0) {
        #pragma unroll
        for (int i = 0; i < RA; i++) {
            int idx = tid + i * THREADS;
            float4 v = make_float4(0.f, 0.f, 0.f, 0.f);
            if (idx < A4) {
                int r = idx / (BK / 4), c = idx % (BK / 4);
                int gm = row0 + r, gk = k0 + c * 4;
                if (gm < M && gk + 4 <= K)
                    v = *(const float4*)(A + (long)gm * K + gk);
            }
            ra[i] = v;
        }
        #pragma unroll
        for (int i = 0; i < RB; i++) {
            int idx = tid + i * THREADS;
            float4 v = make_float4(0.f, 0.f, 0.f, 0.f);
            if (idx < B4) {
                int r = idx / (BN / 4), c = idx % (BN / 4);
                int gk = k0 + r;
                if (gk < K)
                    v = *(const float4*)(B + (long)gk * N + c * 4);
            }
            rb[i] = v;
        }
    };

    auto store_tile = [&]() {
        #pragma unroll
        for (int i = 0; i < RA; i++) {
            int idx = tid + i * THREADS;
            if (idx < A4) {
                int r = idx / (BK / 4), c = (idx % (BK / 4)) * 4;
                float4 v = ra[i];
                unsigned h0, l0, h1, l1, h2, l2, h3, l3;
                split_tf32(v.x, h0, l0); split_tf32(v.y, h1, l1);
                split_tf32(v.z, h2, l2); split_tf32(v.w, h3, l3);
                float4 vh = make_float4(__uint_as_float(h0), __uint_as_float(h1),
                                        __uint_as_float(h2), __uint_as_float(h3));
                float4 vl = make_float4(__uint_as_float(l0), __uint_as_float(l1),
                                        __uint_as_float(l2), __uint_as_float(l3));
                *(float4*)(Ah + r * SA + c) = vh;
                *(float4*)(Al + r * SA + c) = vl;
            }
        }
        #pragma unroll
        for (int i = 0; i < RB; i++) {
            int idx = tid + i * THREADS;
            if (idx < B4) {
                int r = idx / (BN / 4), c = (idx % (BN / 4)) * 4;
                float4 v = rb[i];
                unsigned h0, l0, h1, l1, h2, l2, h3, l3;
                split_tf32(v.x, h0, l0); split_tf32(v.y, h1, l1);
                split_tf32(v.z, h2, l2); split_tf32(v.w, h3, l3);
                float4 vh = make_float4(__uint_as_float(h0), __uint_as_float(h1),
                                        __uint_as_float(h2), __uint_as_float(h3));
                float4 vl = make_float4(__uint_as_float(l0), __uint_as_float(l1),
                                        __uint_as_float(l2), __uint_as_float(l3));
                *(float4*)(Bh + r * SB + c) = vh;
                *(float4*)(Bl + r * SB + c) = vl;
            }
        }
    };

    load_tile(0);
    for (int tt = 0; tt < ntiles; tt++) {
        __syncthreads();
        store_tile();
        __syncthreads();
        if (tt + 1 < ntiles) load_tile((tt + 1) * BK);

        #pragma unroll
        for (int kk = 0; kk < BK; kk += 8) {
            unsigned ah[MT][4], al[MT][4], bh[NT][2], bl[NT][2];
            #pragma unroll
            for (int mi = 0; mi < MT; mi++) {
                int r = wm + mi * 16 + g;
                ah[mi][0] = __float_as_uint(Ah[r * SA + kk + t]);
                ah[mi][1] = __float_as_uint(Ah[(r + 8) * SA + kk + t]);
                ah[mi][2] = __float_as_uint(Ah[r * SA + kk + t + 4]);
                ah[mi][3] = __float_as_uint(Ah[(r + 8) * SA + kk + t + 4]);
                al[mi][0] = __float_as_uint(Al[r * SA + kk + t]);
                al[mi][1] = __float_as_uint(Al[(r + 8) * SA + kk + t]);
                al[mi][2] = __float_as_uint(Al[r * SA + kk + t + 4]);
                al[mi][3] = __float_as_uint(Al[(r + 8) * SA + kk + t + 4]);
            }
            #pragma unroll
            for (int ni = 0; ni < NT; ni++) {
                int c = wn + ni * 8 + g;
                bh[ni][0] = __float_as_uint(Bh[(kk + t) * SB + c]);
                bh[ni][1] = __float_as_uint(Bh[(kk + t + 4) * SB + c]);
                bl[ni][0] = __float_as_uint(Bl[(kk + t) * SB + c]);
                bl[ni][1] = __float_as_uint(Bl[(kk + t + 4) * SB + c]);
            }
            #pragma unroll
            for (int mi = 0; mi < MT; mi++)
                #pragma unroll
                for (int ni = 0; ni < NT; ni++) {
                    MMA_TF32(acc[mi][ni], ah[mi], bh[ni]);
                    MMA_TF32(acc[mi][ni], al[mi], bh[ni]);
                    MMA_TF32(acc[mi][ni], ah[mi], bl[ni]);
                }
        }
    }

    // --- epilogue ---
    #pragma unroll
    for (int mi = 0; mi < MT; mi++) {
        int r = row0 + wm + mi * 16 + g;
        #pragma unroll
        for (int ni = 0; ni < NT; ni++) {
            int c = wn + ni * 8 + 2 * t;
            float bx = 0.f, by = 0.f;
            if (BIAS) { bx = bias[c]; by = bias[c + 1]; }
            if (r < M) {
                float2 v = make_float2(acc[mi][ni][0] + bx, acc[mi][ni][1] + by);
                *(float2*)(C + (long)r * N + c) = v;
            }
            if (r + 8 < M) {
                float2 v = make_float2(acc[mi][ni][2] + bx, acc[mi][ni][3] + by);
                *(float2*)(C + (long)(r + 8) * N + c) = v;
            }
        }
    }
}

// ------------------------------ CSR SpMM -----------------------------------

template <bool RELU>
__global__ void spmm128_kernel(const float* __restrict__ support,
                               const int* __restrict__ offsets,
                               const int* __restrict__ col,
                               const float* __restrict__ val,
                               const float* __restrict__ bias,
                               float* __restrict__ out, int n) {
    int warp = (blockIdx.x * blockDim.x + threadIdx.x) >> 5;
    int lane = threadIdx.x & 31;
    if (warp >= n) return;
    int start = offsets[warp], end = offsets[warp + 1];
    const float4* sup4 = (const float4*)support;
    float4 acc = make_float4(0.f, 0.f, 0.f, 0.f);
    for (int j = start; j < end; j++) {
        int c = col[j];
        float w = val[j];
        float4 s = sup4[c * 32 + lane];
        acc.x += w * s.x; acc.y += w * s.y; acc.z += w * s.z; acc.w += w * s.w;
    }
    float4 bb = ((const float4*)bias)[lane];
    acc.x += bb.x; acc.y += bb.y; acc.z += bb.z; acc.w += bb.w;
    if (RELU) {
        acc.x = fmaxf(acc.x, 0.f); acc.y = fmaxf(acc.y, 0.f);
        acc.z = fmaxf(acc.z, 0.f); acc.w = fmaxf(acc.w, 0.f);
    }
    ((float4*)out)[warp * 32 + lane] = acc;
}

template <bool RELU>
__global__ void spmm64_kernel(const float* __restrict__ support,
                              const int* __restrict__ offsets,
                              const int* __restrict__ col,
                              const float* __restrict__ val,
                              const float* __restrict__ bias,
                              float* __restrict__ out, int n) {
    int warp = (blockIdx.x * blockDim.x + threadIdx.x) >> 5;
    int lane = threadIdx.x & 31;
    if (warp >= n) return;
    int start = offsets[warp], end = offsets[warp + 1];
    const float2* sup2 = (const float2*)support;
    float2 acc = make_float2(0.f, 0.f);
    for (int j = start; j < end; j++) {
        int c = col[j];
        float w = val[j];
        float2 s = sup2[c * 32 + lane];
        acc.x += w * s.x; acc.y += w * s.y;
    }
    float2 bb = ((const float2*)bias)[lane];
    acc.x += bb.x; acc.y += bb.y;
    if (RELU) { acc.x = fmaxf(acc.x, 0.f); acc.y = fmaxf(acc.y, 0.f); }
    ((float2*)out)[warp * 32 + lane] = acc;
}

__global__ void spmm16_kernel(const float* __restrict__ support,
                              const int* __restrict__ offsets,
                              const int* __restrict__ col,
                              const float* __restrict__ val,
                              const float* __restrict__ bias,
                              float* __restrict__ out, int n) {
    int t = blockIdx.x * blockDim.x + threadIdx.x;
    int grp = t >> 4;
    int sub = t & 15;
    if (grp >= n) return;
    int start = offsets[grp], end = offsets[grp + 1];
    float acc = 0.f;
    for (int j = start; j < end; j++) {
        acc += val[j] * support[col[j] * 16 + sub];
    }
    out[grp * 16 + sub] = acc + bias[sub];
}

// ------------------------------ log-softmax --------------------------------

__global__ void logsoftmax16_kernel(const float* __restrict__ in, float* __restrict__ out, int n) {
    int i = blockIdx.x * blockDim.x + threadIdx.x;
    if (i >= n) return;
    float v[16];
    const float4* in4 = (const float4*)(in + i * 16);
    #pragma unroll
    for (int q = 0; q < 4; q++) {
        float4 f = in4[q];
        v[q * 4 + 0] = f.x; v[q * 4 + 1] = f.y; v[q * 4 + 2] = f.z; v[q * 4 + 3] = f.w;
    }
    float m = v[0];
    #pragma unroll
    for (int f = 1; f < 16; f++) m = fmaxf(m, v[f]);
    float s = 0.f;
    #pragma unroll
    for (int f = 0; f < 16; f++) s += expf(v[f] - m);
    float l = logf(s) + m;
    float4* out4 = (float4*)(out + i * 16);
    #pragma unroll
    for (int q = 0; q < 4; q++) {
        float4 f;
        f.x = v[q * 4 + 0] - l; f.y = v[q * 4 + 1] - l;
        f.z = v[q * 4 + 2] - l; f.w = v[q * 4 + 3] - l;
        out4[q] = f;
    }
}

// ------------------------------ launch -------------------------------------

extern "C" void kernel_launch(void* const* d_in, const int* in_sizes, int n_in,
                              void* d_out, int out_size) {
    const float* x  = (const float*)d_in[0];
    const float* ev = (const float*)d_in[1];
    const float* W1 = (const float*)d_in[2];
    const float* b1 = (const float*)d_in[3];
    const float* W2 = (const float*)d_in[4];
    const float* b2 = (const float*)d_in[5];
    const float* W3 = (const float*)d_in[6];
    const float* b3 = (const float*)d_in[7];
    const float* We = (const float*)d_in[8];
    const float* be = (const float*)d_in[9];
    const int* esrc = (const int*)d_in[10];
    const int* edst = (const int*)d_in[11];

    const int N = NN;
    const int E = in_sizes[10];

    float* out1 = (float*)d_out;
    float* out2 = (float*)d_out + (long)N * 16;

    float *p_support, *p_h1, *p_h2, *p_g3, *p_val;
    int *p_counts, *p_offsets, *p_cursor, *p_col;
    cudaGetSymbolAddress((void**)&p_support, g_support);
    cudaGetSymbolAddress((void**)&p_h1, g_h1);
    cudaGetSymbolAddress((void**)&p_h2, g_h2);
    cudaGetSymbolAddress((void**)&p_g3, g_g3);
    cudaGetSymbolAddress((void**)&p_counts, g_counts);
    cudaGetSymbolAddress((void**)&p_offsets, g_offsets);
    cudaGetSymbolAddress((void**)&p_cursor, g_cursor);
    cudaGetSymbolAddress((void**)&p_col, g_col);
    cudaGetSymbolAddress((void**)&p_val, g_val);

    // ---- CSR build ----
    cudaMemsetAsync(p_counts, 0, (N + 1) * sizeof(int), 0);
    cudaMemsetAsync(p_cursor, 0, N * sizeof(int), 0);
    hist_kernel<<<(E + 255) / 256, 256>>>(esrc, p_counts, E);
    scan_kernel<<<1, 1024>>>(p_counts, p_offsets, N);
    scatter_kernel<<<(E + 255) / 256, 256>>>(esrc, edst, ev, p_offsets, p_cursor, p_col, p_val, E);

    dim3 grid(1, (N + 127) / 128);

    // ---- layer 1: support = x@W1 [N,128]; h1 = relu(agg + b1) ----
    tf32_gemm_kernel<128, 128, 16, 2, 4, false><<<grid, 256>>>(N, 128, 500, x, W1, nullptr, p_support);
    spmm128_kernel<true><<<(N * 32 + 255) / 256, 256>>>(p_support, p_offsets, p_col, p_val, b1, p_h1, N);

    // ---- layer 2: support = h1@W2 [N,64]; h2 = relu(agg + b2) ----
    tf32_gemm_kernel<128, 64, 16, 4, 2, false><<<grid, 256>>>(N, 64, 128, p_h1, W2, nullptr, p_support);
    spmm64_kernel<true><<<(N * 32 + 255) / 256, 256>>>(p_support, p_offsets, p_col, p_val, b2, p_h2, N);

    // ---- layer 3: support = h2@W3 [N,16]; out1 = logsoftmax(agg + b3) ----
    tf32_gemm_kernel<128, 16, 16, 8, 1, false><<<grid, 256>>>(N, 16, 64, p_h2, W3, nullptr, p_support);
    spmm16_kernel<<<(N * 16 + 255) / 256, 256>>>(p_support, p_offsets, p_col, p_val, b3, p_g3, N);
    logsoftmax16_kernel<<<(N + 255) / 256, 256>>>(p_g3, out1, N);

    // ---- head 2: out2 = h2@We + be ----
    tf32_gemm_kernel<128, 64, 16, 4, 2, true><<<grid, 256>>>(N, 64, 64, p_h2, We, be, out2);
}

// round 4
// speedup vs baseline: 2.7366x; 1.0655x over previous
#include <cuda_runtime.h>
#include <cuda_bf16.h>
#include <math.h>

// ---------------------------------------------------------------------------
// GCN 3-layer. Round 2: tf32 tensor-core GEMMs with ping-pong smem +
// register-fragment double buffering; shuffle-based CSR scan; fused
// spmm16+log_softmax. CSR gather-side SpMM for aggregation.
// ---------------------------------------------------------------------------

#define NN 50000
#define EE 800000

__device__ float g_support[NN * 128];
__device__ float g_h1[NN * 128];
__device__ float g_h2[NN * 64];
__device__ int   g_counts[NN + 1];
__device__ int   g_offsets[NN + 1];
__device__ int   g_cursor[NN];
__device__ int   g_col[EE];
__device__ float g_val[EE];

// ------------------------------ CSR build ----------------------------------

__global__ void hist_kernel(const int* __restrict__ src, int* __restrict__ counts, int E) {
    int i = blockIdx.x * blockDim.x + threadIdx.x;
    if (i < E) atomicAdd(&counts[src[i]], 1);
}

// single block, 1024 threads, warp-shuffle scan over thread-local chunks
__global__ void scan_kernel(const int* __restrict__ counts, int* __restrict__ offsets, int n) {
    const int T = 1024;
    __shared__ int wsum[32];
    int tid = threadIdx.x;
    int per = (n + T - 1) / T;
    int beg = tid * per;
    int end = min(beg + per, n);
    int sum = 0;
    for (int i = beg; i < end; i++) sum += counts[i];
    int lane = tid & 31, wid = tid >> 5;
    int v = sum;
    #pragma unroll
    for (int off = 1; off < 32; off <<= 1) {
        int t2 = __shfl_up_sync(0xffffffffu, v, off);
        if (lane >= off) v += t2;
    }
    if (lane == 31) wsum[wid] = v;
    __syncthreads();
    if (wid == 0) {
        int w = wsum[lane];
        #pragma unroll
        for (int off = 1; off < 32; off <<= 1) {
            int t2 = __shfl_up_sync(0xffffffffu, w, off);
            if (lane >= off) w += t2;
        }
        wsum[lane] = w;
    }
    __syncthreads();
    int pre = v - sum + (wid > 0 ? wsum[wid - 1] : 0);
    int run = pre;
    for (int i = beg; i < end; i++) { offsets[i] = run; run += counts[i]; }
    if (end == n) offsets[n] = run;
}

__global__ void scatter_kernel(const int* __restrict__ src, const int* __restrict__ dst,
                               const float* __restrict__ ev,
                               const int* __restrict__ offsets, int* __restrict__ cursor,
                               int* __restrict__ col, float* __restrict__ val, int E) {
    int i = blockIdx.x * blockDim.x + threadIdx.x;
    if (i < E) {
        int s = src[i];
        int pos = offsets[s] + atomicAdd(&cursor[s], 1);
        col[pos] = dst[i];
        val[pos] = ev[i];
    }
}

// ------------------------------ tf32 GEMM ----------------------------------
// C[M,N] = A[M,K] @ B[K,N] (+bias). mma m16n8k8 tf32, 2-term hi/lo split
// (3 MMAs per logical MMA). Ping-pong smem + fragment double buffering.
// Requires N == BN (grid.x == 1), K % 4 == 0.

__device__ __forceinline__ void split_tf32(float x, unsigned& hi, unsigned& lo) {
    unsigned h;
    asm("cvt.rna.tf32.f32 %0, %1;" : "=r"(h) : "f"(x));
    float r = x - __uint_as_float(h);
    unsigned l;
    asm("cvt.rna.tf32.f32 %0, %1;" : "=r"(l) : "f"(r));
    hi = h; lo = l;
}

#define MMA_TF32(c, a, b)                                                    \
    asm volatile(                                                            \
        "mma.sync.aligned.m16n8k8.row.col.f32.tf32.tf32.f32 "                \
        "{%0,%1,%2,%3}, {%4,%5,%6,%7}, {%8,%9}, {%0,%1,%2,%3};\n"            \
        : "+f"((c)[0]), "+f"((c)[1]), "+f"((c)[2]), "+f"((c)[3])             \
        : "r"((a)[0]), "r"((a)[1]), "r"((a)[2]), "r"((a)[3]),                \
          "r"((b)[0]), "r"((b)[1]))

constexpr int gemm_smem_bytes(int BM, int BN, int BK) {
    int SA = BK + 4, SB = BN + 8;
    return (2 * 2 * BM * SA + 2 * 2 * BK * SB) * 4;
}

template <int BM, int BN, int BK, int WARPS_M, int WARPS_N, bool BIAS>
__global__ void __launch_bounds__(32 * WARPS_M * WARPS_N)
tf32_gemm_kernel(int M, int N, int K,
                 const float* __restrict__ A, const float* __restrict__ B,
                 const float* __restrict__ bias, float* __restrict__ C) {
    constexpr int THREADS = 32 * WARPS_M * WARPS_N;
    constexpr int WM = BM / WARPS_M, WN = BN / WARPS_N;
    constexpr int MT = WM / 16, NT = WN / 8;
    constexpr int SA = BK + 4;
    constexpr int SB = BN + 8;
    constexpr int A4 = BM * BK / 4, B4 = BK * BN / 4;
    constexpr int RA = (A4 + THREADS - 1) / THREADS;
    constexpr int RB = (B4 + THREADS - 1) / THREADS;
    constexpr int ASZ = BM * SA, BSZ = BK * SB;

    extern __shared__ float smem[];
    float* Ah = smem;                 // [2][ASZ]
    float* Al = Ah + 2 * ASZ;
    float* Bh = Al + 2 * ASZ;         // [2][BSZ]
    float* Bl = Bh + 2 * BSZ;

    const int tid = threadIdx.x;
    const int warp = tid >> 5, lane = tid & 31;
    const int wm = (warp / WARPS_N) * WM;
    const int wn = (warp % WARPS_N) * WN;
    const int g = lane >> 2, t = lane & 3;
    const int row0 = blockIdx.y * BM;

    float acc[MT][NT][4];
    #pragma unroll
    for (int mi = 0; mi < MT; mi++)
        #pragma unroll
        for (int ni = 0; ni < NT; ni++)
            #pragma unroll
            for (int q = 0; q < 4; q++) acc[mi][ni][q] = 0.f;

    float4 ra[RA], rb[RB];
    const int ntiles = (K + BK - 1) / BK;

    auto load_tile = [&](int k0) {
        #pragma unroll
        for (int i = 0; i < RA; i++) {
            int idx = tid + i * THREADS;
            float4 v = make_float4(0.f, 0.f, 0.f, 0.f);
            if (idx < A4) {
                int r = idx / (BK / 4), c = idx % (BK / 4);
                int gm = row0 + r, gk = k0 + c * 4;
                if (gm < M && gk + 4 <= K)
                    v = *(const float4*)(A + (long)gm * K + gk);
            }
            ra[i] = v;
        }
        #pragma unroll
        for (int i = 0; i < RB; i++) {
            int idx = tid + i * THREADS;
            float4 v = make_float4(0.f, 0.f, 0.f, 0.f);
            if (idx < B4) {
                int r = idx / (BN / 4), c = idx % (BN / 4);
                int gk = k0 + r;
                if (gk < K)
                    v = *(const float4*)(B + (long)gk * N + c * 4);
            }
            rb[i] = v;
        }
    };

    auto store_tile = [&](int b) {
        float* ah = Ah + b * ASZ; float* al = Al + b * ASZ;
        float* bh = Bh + b * BSZ; float* bl = Bl + b * BSZ;
        #pragma unroll
        for (int i = 0; i < RA; i++) {
            int idx = tid + i * THREADS;
            if (idx < A4) {
                int r = idx / (BK / 4), c = (idx % (BK / 4)) * 4;
                float4 v = ra[i];
                unsigned h0, l0, h1, l1, h2, l2, h3, l3;
                split_tf32(v.x, h0, l0); split_tf32(v.y, h1, l1);
                split_tf32(v.z, h2, l2); split_tf32(v.w, h3, l3);
                float4 vh = make_float4(__uint_as_float(h0), __uint_as_float(h1),
                                        __uint_as_float(h2), __uint_as_float(h3));
                float4 vl = make_float4(__uint_as_float(l0), __uint_as_float(l1),
                                        __uint_as_float(l2), __uint_as_float(l3));
                *(float4*)(ah + r * SA + c) = vh;
                *(float4*)(al + r * SA + c) = vl;
            }
        }
        #pragma unroll
        for (int i = 0; i < RB; i++) {
            int idx = tid + i * THREADS;
            if (idx < B4) {
                int r = idx / (BN / 4), c = (idx % (BN / 4)) * 4;
                float4 v = rb[i];
                unsigned h0, l0, h1, l1, h2, l2, h3, l3;
                split_tf32(v.x, h0, l0); split_tf32(v.y, h1, l1);
                split_tf32(v.z, h2, l2); split_tf32(v.w, h3, l3);
                float4 vh = make_float4(__uint_as_float(h0), __uint_as_float(h1),
                                        __uint_as_float(h2), __uint_as_float(h3));
                float4 vl = make_float4(__uint_as_float(l0), __uint_as_float(l1),
                                        __uint_as_float(l2), __uint_as_float(l3));
                *(float4*)(bh + r * SB + c) = vh;
                *(float4*)(bl + r * SB + c) = vl;
            }
        }
    };

    // prologue: tile 0 into buffer 0
    load_tile(0);
    store_tile(0);
    __syncthreads();

    for (int tt = 0; tt < ntiles; tt++) {
        if (tt + 1 < ntiles) load_tile((tt + 1) * BK);  // LDG issue (hidden by MMAs)

        const float* cAh = Ah + (tt & 1) * ASZ;
        const float* cAl = Al + (tt & 1) * ASZ;
        const float* cBh = Bh + (tt & 1) * BSZ;
        const float* cBl = Bl + (tt & 1) * BSZ;

        unsigned fah[2][MT][4], fal[2][MT][4], fbh[2][NT][2], fbl[2][NT][2];

        auto load_frags = [&](int s, int kk) {
            #pragma unroll
            for (int mi = 0; mi < MT; mi++) {
                int r = wm + mi * 16 + g;
                fah[s][mi][0] = __float_as_uint(cAh[r * SA + kk + t]);
                fah[s][mi][1] = __float_as_uint(cAh[(r + 8) * SA + kk + t]);
                fah[s][mi][2] = __float_as_uint(cAh[r * SA + kk + t + 4]);
                fah[s][mi][3] = __float_as_uint(cAh[(r + 8) * SA + kk + t + 4]);
                fal[s][mi][0] = __float_as_uint(cAl[r * SA + kk + t]);
                fal[s][mi][1] = __float_as_uint(cAl[(r + 8) * SA + kk + t]);
                fal[s][mi][2] = __float_as_uint(cAl[r * SA + kk + t + 4]);
                fal[s][mi][3] = __float_as_uint(cAl[(r + 8) * SA + kk + t + 4]);
            }
            #pragma unroll
            for (int ni = 0; ni < NT; ni++) {
                int c = wn + ni * 8 + g;
                fbh[s][ni][0] = __float_as_uint(cBh[(kk + t) * SB + c]);
                fbh[s][ni][1] = __float_as_uint(cBh[(kk + t + 4) * SB + c]);
                fbl[s][ni][0] = __float_as_uint(cBl[(kk + t) * SB + c]);
                fbl[s][ni][1] = __float_as_uint(cBl[(kk + t + 4) * SB + c]);
            }
        };

        load_frags(0, 0);
        #pragma unroll
        for (int k8 = 0; k8 < BK / 8; k8++) {
            int s = k8 & 1;
            if (k8 + 1 < BK / 8) load_frags(s ^ 1, (k8 + 1) * 8);
            #pragma unroll
            for (int mi = 0; mi < MT; mi++)
                #pragma unroll
                for (int ni = 0; ni < NT; ni++) {
                    MMA_TF32(acc[mi][ni], fah[s][mi], fbh[s][ni]);
                    MMA_TF32(acc[mi][ni], fal[s][mi], fbh[s][ni]);
                    MMA_TF32(acc[mi][ni], fah[s][mi], fbl[s][ni]);
                }
        }

        if (tt + 1 < ntiles) store_tile((tt + 1) & 1);
        __syncthreads();
    }

    // epilogue
    #pragma unroll
    for (int mi = 0; mi < MT; mi++) {
        int r = row0 + wm + mi * 16 + g;
        #pragma unroll
        for (int ni = 0; ni < NT; ni++) {
            int c = wn + ni * 8 + 2 * t;
            float bx = 0.f, by = 0.f;
            if (BIAS) { bx = bias[c]; by = bias[c + 1]; }
            if (r < M) {
                float2 v = make_float2(acc[mi][ni][0] + bx, acc[mi][ni][1] + by);
                *(float2*)(C + (long)r * N + c) = v;
            }
            if (r + 8 < M) {
                float2 v = make_float2(acc[mi][ni][2] + bx, acc[mi][ni][3] + by);
                *(float2*)(C + (long)(r + 8) * N + c) = v;
            }
        }
    }
}

// ------------------------------ CSR SpMM -----------------------------------

template <bool RELU>
__global__ void spmm128_kernel(const float* __restrict__ support,
                               const int* __restrict__ offsets,
                               const int* __restrict__ col,
                               const float* __restrict__ val,
                               const float* __restrict__ bias,
                               float* __restrict__ out, int n) {
    int warp = (blockIdx.x * blockDim.x + threadIdx.x) >> 5;
    int lane = threadIdx.x & 31;
    if (warp >= n) return;
    int start = offsets[warp], end = offsets[warp + 1];
    const float4* sup4 = (const float4*)support;
    float4 acc = make_float4(0.f, 0.f, 0.f, 0.f);
    for (int j = start; j < end; j++) {
        int c = col[j];
        float w = val[j];
        float4 s = sup4[c * 32 + lane];
        acc.x += w * s.x; acc.y += w * s.y; acc.z += w * s.z; acc.w += w * s.w;
    }
    float4 bb = ((const float4*)bias)[lane];
    acc.x += bb.x; acc.y += bb.y; acc.z += bb.z; acc.w += bb.w;
    if (RELU) {
        acc.x = fmaxf(acc.x, 0.f); acc.y = fmaxf(acc.y, 0.f);
        acc.z = fmaxf(acc.z, 0.f); acc.w = fmaxf(acc.w, 0.f);
    }
    ((float4*)out)[warp * 32 + lane] = acc;
}

template <bool RELU>
__global__ void spmm64_kernel(const float* __restrict__ support,
                              const int* __restrict__ offsets,
                              const int* __restrict__ col,
                              const float* __restrict__ val,
                              const float* __restrict__ bias,
                              float* __restrict__ out, int n) {
    int warp = (blockIdx.x * blockDim.x + threadIdx.x) >> 5;
    int lane = threadIdx.x & 31;
    if (warp >= n) return;
    int start = offsets[warp], end = offsets[warp + 1];
    const float2* sup2 = (const float2*)support;
    float2 acc = make_float2(0.f, 0.f);
    for (int j = start; j < end; j++) {
        int c = col[j];
        float w = val[j];
        float2 s = sup2[c * 32 + lane];
        acc.x += w * s.x; acc.y += w * s.y;
    }
    float2 bb = ((const float2*)bias)[lane];
    acc.x += bb.x; acc.y += bb.y;
    if (RELU) { acc.x = fmaxf(acc.x, 0.f); acc.y = fmaxf(acc.y, 0.f); }
    ((float2*)out)[warp * 32 + lane] = acc;
}

// fused spmm(D=16) + bias + log_softmax (16-lane groups, shuffle reductions)
__global__ void spmm16_lsm_kernel(const float* __restrict__ support,
                                  const int* __restrict__ offsets,
                                  const int* __restrict__ col,
                                  const float* __restrict__ val,
                                  const float* __restrict__ bias,
                                  float* __restrict__ out, int n) {
    int t = blockIdx.x * blockDim.x + threadIdx.x;
    int grp = t >> 4;
    int sub = t & 15;
    bool active = grp < n;
    int g2 = active ? grp : (n - 1);
    int start = offsets[g2], end = offsets[g2 + 1];
    float acc = 0.f;
    for (int j = start; j < end; j++)
        acc += val[j] * support[col[j] * 16 + sub];
    acc += bias[sub];
    float m = acc;
    #pragma unroll
    for (int off = 8; off >= 1; off >>= 1)
        m = fmaxf(m, __shfl_xor_sync(0xffffffffu, m, off, 16));
    float s = expf(acc - m);
    #pragma unroll
    for (int off = 8; off >= 1; off >>= 1)
        s += __shfl_xor_sync(0xffffffffu, s, off, 16);
    if (active) out[grp * 16 + sub] = acc - (logf(s) + m);
}

// ------------------------------ launch -------------------------------------

extern "C" void kernel_launch(void* const* d_in, const int* in_sizes, int n_in,
                              void* d_out, int out_size) {
    const float* x  = (const float*)d_in[0];
    const float* ev = (const float*)d_in[1];
    const float* W1 = (const float*)d_in[2];
    const float* b1 = (const float*)d_in[3];
    const float* W2 = (const float*)d_in[4];
    const float* b2 = (const float*)d_in[5];
    const float* W3 = (const float*)d_in[6];
    const float* b3 = (const float*)d_in[7];
    const float* We = (const float*)d_in[8];
    const float* be = (const float*)d_in[9];
    const int* esrc = (const int*)d_in[10];
    const int* edst = (const int*)d_in[11];

    const int N = NN;
    const int E = in_sizes[10];

    float* out1 = (float*)d_out;
    float* out2 = (float*)d_out + (long)N * 16;

    float *p_support, *p_h1, *p_h2, *p_val;
    int *p_counts, *p_offsets, *p_cursor, *p_col;
    cudaGetSymbolAddress((void**)&p_support, g_support);
    cudaGetSymbolAddress((void**)&p_h1, g_h1);
    cudaGetSymbolAddress((void**)&p_h2, g_h2);
    cudaGetSymbolAddress((void**)&p_counts, g_counts);
    cudaGetSymbolAddress((void**)&p_offsets, g_offsets);
    cudaGetSymbolAddress((void**)&p_cursor, g_cursor);
    cudaGetSymbolAddress((void**)&p_col, g_col);
    cudaGetSymbolAddress((void**)&p_val, g_val);

    // smem limits for the big-tile GEMMs (dynamic smem > 48KB)
    constexpr int S1 = gemm_smem_bytes(128, 128, 16);  // 75776
    constexpr int S2 = gemm_smem_bytes(128, 64, 16);   // 59.4KB
    constexpr int S3 = gemm_smem_bytes(128, 16, 16);   // 46KB
    cudaFuncSetAttribute(tf32_gemm_kernel<128, 128, 16, 2, 4, false>,
                         cudaFuncAttributeMaxDynamicSharedMemorySize, S1);
    cudaFuncSetAttribute(tf32_gemm_kernel<128, 64, 16, 4, 2, false>,
                         cudaFuncAttributeMaxDynamicSharedMemorySize, S2);
    cudaFuncSetAttribute(tf32_gemm_kernel<128, 64, 16, 4, 2, true>,
                         cudaFuncAttributeMaxDynamicSharedMemorySize, S2);
    cudaFuncSetAttribute(tf32_gemm_kernel<128, 16, 16, 8, 1, false>,
                         cudaFuncAttributeMaxDynamicSharedMemorySize, S3);

    // ---- CSR build ----
    cudaMemsetAsync(p_counts, 0, (N + 1) * sizeof(int), 0);
    cudaMemsetAsync(p_cursor, 0, N * sizeof(int), 0);
    hist_kernel<<<(E + 255) / 256, 256>>>(esrc, p_counts, E);
    scan_kernel<<<1, 1024>>>(p_counts, p_offsets, N);
    scatter_kernel<<<(E + 255) / 256, 256>>>(esrc, edst, ev, p_offsets, p_cursor, p_col, p_val, E);

    dim3 grid(1, (N + 127) / 128);

    // ---- layer 1: support = x@W1 [N,128]; h1 = relu(agg + b1) ----
    tf32_gemm_kernel<128, 128, 16, 2, 4, false><<<grid, 256, S1>>>(N, 128, 500, x, W1, nullptr, p_support);
    spmm128_kernel<true><<<(N * 32 + 255) / 256, 256>>>(p_support, p_offsets, p_col, p_val, b1, p_h1, N);

    // ---- layer 2: support = h1@W2 [N,64]; h2 = relu(agg + b2) ----
    tf32_gemm_kernel<128, 64, 16, 4, 2, false><<<grid, 256, S2>>>(N, 64, 128, p_h1, W2, nullptr, p_support);
    spmm64_kernel<true><<<(N * 32 + 255) / 256, 256>>>(p_support, p_offsets, p_col, p_val, b2, p_h2, N);

    // ---- layer 3: support = h2@W3 [N,16]; out1 = log_softmax(agg + b3) ----
    tf32_gemm_kernel<128, 16, 16, 8, 1, false><<<grid, 256, S3>>>(N, 16, 64, p_h2, W3, nullptr, p_support);
    spmm16_lsm_kernel<<<(N * 16 + 255) / 256, 256>>>(p_support, p_offsets, p_col, p_val, b3, out1, N);

    // ---- head 2: out2 = h2@We + be ----
    tf32_gemm_kernel<128, 64, 16, 4, 2, true><<<grid, 256, S2>>>(N, 64, 64, p_h2, We, be, out2);
}